// round 16
// baseline (speedup 1.0000x reference)
#include <cuda_runtime.h>
#include <cuda.h>
#include <cuda_fp16.h>

typedef unsigned int u32;
typedef unsigned long long u64;

#define BB 4
#define SS 2048
#define EE 1024
#define HH 16
#define DD 64
#define QQ 4
#define MM (BB*SS)     /* 8192 tokens */
#define NQKV 6144

// ───────── scratch (allocation-free rule: __device__ globals) ─────────
__device__ __half g_qf [(size_t)MM * 4096];    // q in mma-A-fragment layout
__device__ __half g_kvf[(size_t)MM * 2048];    // k|v contiguous per token
__device__ __half g_z  [(size_t)MM * EE];      // attn output, fp16
__device__ float  g_bqkv[NQKV];

__device__ __half g_xh[(size_t)MM*EE];
__device__ __half g_wqkv[(size_t)NQKV*EE];
__device__ __half g_wo[(size_t)EE*EE];

__device__ __forceinline__ u32 smem_u32(const void* p) {
    u32 a;
    asm("{ .reg .u64 t; cvta.to.shared.u64 t, %1; cvt.u32.u64 %0, t; }"
        : "=r"(a) : "l"(p));
    return a;
}
__device__ __forceinline__ void ldsm4(u32 addr, u32* r) {
    asm volatile("ldmatrix.sync.aligned.m8n8.x4.shared.b16 {%0,%1,%2,%3}, [%4];"
                 : "=r"(r[0]), "=r"(r[1]), "=r"(r[2]), "=r"(r[3]) : "r"(addr));
}
__device__ __forceinline__ void ldsm4t(u32 addr, u32* r) {
    asm volatile("ldmatrix.sync.aligned.m8n8.x4.trans.shared.b16 {%0,%1,%2,%3}, [%4];"
                 : "=r"(r[0]), "=r"(r[1]), "=r"(r[2]), "=r"(r[3]) : "r"(addr));
}
__device__ __forceinline__ void mma16816(float* c, const u32* a, const u32* b) {
    asm volatile(
        "mma.sync.aligned.m16n8k16.row.col.f32.f16.f16.f32 "
        "{%0,%1,%2,%3}, {%4,%5,%6,%7}, {%8,%9}, {%0,%1,%2,%3};"
        : "+f"(c[0]), "+f"(c[1]), "+f"(c[2]), "+f"(c[3])
        : "r"(a[0]), "r"(a[1]), "r"(a[2]), "r"(a[3]), "r"(b[0]), "r"(b[1]));
}
__device__ __forceinline__ void tma2d(u32 saddr, const CUtensorMap* m,
                                      int cx, int cy, u32 mbar) {
    asm volatile(
        "cp.async.bulk.tensor.2d.shared::cta.global.tile.mbarrier::complete_tx::bytes "
        "[%0], [%1, {%2, %3}], [%4];"
        :: "r"(saddr), "l"(m), "r"(cx), "r"(cy), "r"(mbar) : "memory");
}
#define MBAR_INIT(addr, cnt) \
    asm volatile("mbarrier.init.shared.b64 [%0], %1;" :: "r"(addr), "r"(cnt) : "memory")
#define MBAR_EXPECT(addr, bytes) \
    asm volatile("mbarrier.arrive.expect_tx.shared.b64 _, [%0], %1;" \
                 :: "r"(addr), "r"(bytes) : "memory")
__device__ __forceinline__ void mbar_wait(u32 addr, u32 parity) {
    asm volatile(
        "{\n\t.reg .pred P;\n\t"
        "W%=:\n\t"
        "mbarrier.try_wait.parity.acquire.cta.shared::cta.b64 P, [%0], %1, 0x989680;\n\t"
        "@P bra D%=;\n\t"
        "bra W%=;\n\t"
        "D%=:\n\t}"
        :: "r"(addr), "r"(parity) : "memory");
}
#define SWZ(off) ((u32)(off) ^ ((((u32)(off)) >> 3) & 0x70))

// ───────── fused fp32→fp16 conversion ─────────
#define C_X  2097152
#define C_WQ (C_X + 1048576)
#define C_WK (C_WQ + 262144)
#define C_WV (C_WK + 262144)
#define C_WO (C_WV + 262144)

__global__ __launch_bounds__(256) void conv_all(
    const float* __restrict__ x,  const float* __restrict__ Wq,
    const float* __restrict__ Wk, const float* __restrict__ Wv,
    const float* __restrict__ Wo,
    __half* __restrict__ xh, __half* __restrict__ wqkv, __half* __restrict__ wo)
{
    int i = blockIdx.x * blockDim.x + threadIdx.x;
    const float* s; __half* d; int off;
    if (i < C_X)       { s = x;  d = xh;                           off = i; }
    else if (i < C_WQ) { s = Wq; d = wqkv;                         off = i - C_X; }
    else if (i < C_WK) { s = Wk; d = wqkv + (size_t)4096*EE;       off = i - C_WQ; }
    else if (i < C_WV) { s = Wv; d = wqkv + (size_t)5120*EE;       off = i - C_WK; }
    else               { s = Wo; d = wo;                           off = i - C_WV; }
    float4 v = ((const float4*)s)[off];
    ushort4 ho;
    ho.x = __half_as_ushort(__float2half_rn(v.x));
    ho.y = __half_as_ushort(__float2half_rn(v.y));
    ho.z = __half_as_ushort(__float2half_rn(v.z));
    ho.w = __half_as_ushort(__float2half_rn(v.w));
    ((ushort4*)d)[off] = ho;
}

__global__ __launch_bounds__(256) void bias_concat(
    const float* __restrict__ bq, const float* __restrict__ bk,
    const float* __restrict__ bv, float* __restrict__ dst)
{
    int i = blockIdx.x * blockDim.x + threadIdx.x;
    if (i >= NQKV) return;
    float v;
    if (i < 4096)      v = bq[i];
    else if (i < 5120) v = bk[i - 4096];
    else               v = bv[i - 5120];
    dst[i] = v;
}

// ═════ 1-PASS fp16 GEMM, 4-stage TMA. MA = m-frags/warp (BM = MA*32).
//       QPERM: q cols → A-fragment layout (qf), k|v cols → kvf. ═════
#define CHK 64

template<int OUT16, int MA, int QPERM>
__global__ __launch_bounds__(256, 1) void hgemm1(
    const __grid_constant__ CUtensorMap tA,
    const __grid_constant__ CUtensorMap tB,
    const float* __restrict__ bias, void* __restrict__ Cv,
    __half* __restrict__ qf, __half* __restrict__ kvf,
    int N_, int K, int ny0)
{
    constexpr u32 ABYT = (u32)MA * 32u * 128u;     // A tile bytes
    constexpr u32 STB  = ABYT + 32768u;            // stage bytes
    constexpr u32 CTRL = 4u * STB;

    extern __shared__ __align__(1024) char smem[];
    const u32 sb   = smem_u32(smem);
    const int tid  = threadIdx.x;
    const int wid  = tid >> 5;
    const int lane = tid & 31;
    const int m0   = blockIdx.y * (MA * 32);
    const int n0   = blockIdx.x * 256;
    const int wm   = (wid & 1) * (MA * 16);
    const int wn   = (wid >> 1) * 64;
    const int nch  = K / CHK;

    float acc[MA][8][4];
    #pragma unroll
    for (int i = 0; i < MA; i++)
        #pragma unroll
        for (int j = 0; j < 8; j++)
            #pragma unroll
            for (int t = 0; t < 4; t++) acc[i][j][t] = 0.f;

    if (tid == 0) {
        #pragma unroll
        for (int s = 0; s < 4; s++) MBAR_INIT(sb + CTRL + s * 8, 1);
    }
    __syncthreads();

    auto issue = [&](int c) {
        if (tid == 0) {
            const int st   = c & 3;
            const u32 mbar = sb + CTRL + st * 8;
            const u32 s0   = sb + st * STB;
            MBAR_EXPECT(mbar, STB);
            int kc = c * CHK;
            tma2d(s0,        &tA, kc, m0, mbar);
            tma2d(s0 + ABYT, &tB, kc, ny0 + n0, mbar);
        }
    };

    issue(0); issue(1); issue(2); issue(3);

    for (int c = 0; c < nch; c++) {
        const int st = c & 3;
        mbar_wait(sb + CTRL + st * 8, (c >> 2) & 1);
        const u32 s0 = sb + st * STB;

        #pragma unroll
        for (int ks = 0; ks < 4; ks++) {
            const int k0 = ks * 16;
            u32 a[MA][4], b[4][4];
            #pragma unroll
            for (int ma = 0; ma < MA; ma++) {
                int row  = wm + ma * 16 + ((lane >> 3) & 1) * 8 + (lane & 7);
                int colB = (k0 + (lane >> 4) * 8) * 2;
                ldsm4(s0 + SWZ(row * 128 + colB), a[ma]);
            }
            #pragma unroll
            for (int j = 0; j < 4; j++) {
                int row  = wn + j * 16 + (lane >> 4) * 8 + (lane & 7);
                int colB = (k0 + ((lane >> 3) & 1) * 8) * 2;
                ldsm4(s0 + ABYT + SWZ(row * 128 + colB), b[j]);
            }
            #pragma unroll
            for (int j = 0; j < 4; j++)
                #pragma unroll
                for (int ma = 0; ma < MA; ma++) {
                    mma16816(acc[ma][j*2+0], a[ma], &b[j][0]);
                    mma16816(acc[ma][j*2+1], a[ma], &b[j][2]);
                }
        }
        __syncthreads();
        if (c + 4 < nch) issue(c + 4);
    }

    #pragma unroll
    for (int ma = 0; ma < MA; ma++) {
        #pragma unroll
        for (int nb = 0; nb < 8; nb++) {
            int row = m0 + wm + ma * 16 + (lane >> 2);
            int col = n0 + wn + nb * 8 + (lane & 3) * 2;
            float b0 = bias[col], b1 = bias[col + 1];
            float v00 = acc[ma][nb][0] + b0, v01 = acc[ma][nb][1] + b1;
            float v10 = acc[ma][nb][2] + b0, v11 = acc[ma][nb][3] + b1;
            if (QPERM) {
                __half2 lo = __floats2half2_rn(v00, v01);
                __half2 hi = __floats2half2_rn(v10, v11);
                if (col < 4096) {
                    int qi = col >> 10, h = (col >> 6) & 15, d = col & 63;
                    int f  = qi * 4 + (d >> 4);
                    int lp = (h & 7) * 4 + ((d >> 1) & 3);
                    int rg = ((d & 8) >> 2) + (h >> 3);
                    size_t base = (size_t)f * 256 + lp * 8 + rg * 2;
                    *(__half2*)(qf + (size_t)row * 4096 + base)       = lo;
                    *(__half2*)(qf + (size_t)(row + 8) * 4096 + base) = hi;
                } else {
                    int cc = col - 4096;
                    *(__half2*)(kvf + (size_t)row * 2048 + cc)       = lo;
                    *(__half2*)(kvf + (size_t)(row + 8) * 2048 + cc) = hi;
                }
            } else if (OUT16) {
                __half* C = (__half*)Cv;
                *(__half2*)(C + (size_t)row * N_ + col)       = __floats2half2_rn(v00, v01);
                *(__half2*)(C + (size_t)(row + 8) * N_ + col) = __floats2half2_rn(v10, v11);
            } else {
                float* C = (float*)Cv;
                *(float2*)(C + (size_t)row * N_ + col)       = make_float2(v00, v01);
                *(float2*)(C + (size_t)(row + 8) * N_ + col) = make_float2(v10, v11);
            }
        }
    }
}

// ───────── attention v6: q frags direct from global; only k|v in smem ─────────
#define ATOK 8
#define TOKB 4096
#define ASMEM (ATOK*TOKB)

__global__ __launch_bounds__(256) void attn_kernel(
    const __half* __restrict__ qf, const __half* __restrict__ kvf,
    __half* __restrict__ z)
{
    extern __shared__ __align__(1024) char smem[];
    const u32 sb   = smem_u32(smem);
    const int tid  = threadIdx.x;
    const int lane = tid & 31;
    const int w    = tid >> 5;
    const int n    = blockIdx.x * ATOK + w;
    const int b    = n >> 11;
    const int sp   = n & 2047;
    const u32 tb   = sb + w * TOKB;

    // ── warp-private staging of k|v (256 uint4 = 4 KB), 8 per lane ──
    {
        const uint4* src = (const uint4*)kvf + (size_t)n * 256;
        #pragma unroll
        for (int i = 0; i < 8; i++) {
            int idx = lane + i * 32;
            uint4 val = src[idx];
            *(uint4*)(smem + (u32)w * TOKB + SWZ(idx * 16)) = val;
        }
    }
    __syncwarp();

    // k b-frags (rows 0..15)
    u32 kb[4][4];
    #pragma unroll
    for (int ks = 0; ks < 4; ks++) {
        int row  = (lane >> 4) * 8 + (lane & 7);
        int colB = (ks * 16 + ((lane >> 3) & 1) * 8) * 2;
        ldsm4(tb + SWZ(row * 128 + colB), kb[ks]);
    }
    // v b-frags via trans ldsm (rows 16..31)
    u32 vb[4][4];
    #pragma unroll
    for (int nb4 = 0; nb4 < 4; nb4++) {
        int row  = 16 + (lane & 15);
        int colB = (nb4 * 16 + (lane >> 4) * 8) * 2;
        ldsm4t(tb + SWZ(row * 128 + colB), vb[nb4]);
    }

    const uint4* qsrc = (const uint4*)qf + (size_t)n * 512;

    float psum[8];
    #pragma unroll
    for (int i = 0; i < 8; i++) psum[i] = 0.f;

    #pragma unroll
    for (int qi = 0; qi < QQ; qi++) {
        u32 qa[4][4];
        #pragma unroll
        for (int ks = 0; ks < 4; ks++) {
            uint4 u = qsrc[(qi * 4 + ks) * 32 + lane];   // coalesced A-frag
            qa[ks][0] = u.x; qa[ks][1] = u.y; qa[ks][2] = u.z; qa[ks][3] = u.w;
        }
        float sc[2][4];
        #pragma unroll
        for (int t = 0; t < 4; t++) { sc[0][t] = 0.f; sc[1][t] = 0.f; }
        #pragma unroll
        for (int ks = 0; ks < 4; ks++) {
            mma16816(sc[0], qa[ks], &kb[ks][0]);
            mma16816(sc[1], qa[ks], &kb[ks][2]);
        }
        #pragma unroll
        for (int t = 0; t < 4; t++) { sc[0][t] *= 0.125f; sc[1][t] *= 0.125f; }
        float m0 = fmaxf(fmaxf(sc[0][0], sc[0][1]), fmaxf(sc[1][0], sc[1][1]));
        float m1 = fmaxf(fmaxf(sc[0][2], sc[0][3]), fmaxf(sc[1][2], sc[1][3]));
        #pragma unroll
        for (int o = 1; o <= 2; o <<= 1) {
            m0 = fmaxf(m0, __shfl_xor_sync(~0u, m0, o));
            m1 = fmaxf(m1, __shfl_xor_sync(~0u, m1, o));
        }
        float e00 = __expf(sc[0][0] - m0), e01 = __expf(sc[0][1] - m0);
        float e10 = __expf(sc[1][0] - m0), e11 = __expf(sc[1][1] - m0);
        float f00 = __expf(sc[0][2] - m1), f01 = __expf(sc[0][3] - m1);
        float f10 = __expf(sc[1][2] - m1), f11 = __expf(sc[1][3] - m1);
        float s0 = e00 + e01 + e10 + e11;
        float s1 = f00 + f01 + f10 + f11;
        #pragma unroll
        for (int o = 1; o <= 2; o <<= 1) {
            s0 += __shfl_xor_sync(~0u, s0, o);
            s1 += __shfl_xor_sync(~0u, s1, o);
        }
        float i0 = 1.f / s0, i1 = 1.f / s1;
        psum[0] += e00 * i0; psum[1] += e01 * i0;
        psum[2] += f00 * i1; psum[3] += f01 * i1;
        psum[4] += e10 * i0; psum[5] += e11 * i0;
        psum[6] += f10 * i1; psum[7] += f11 * i1;
    }

    u32 pa[4];
    {
        __half2 h0 = __floats2half2_rn(psum[0], psum[1]);
        __half2 h1 = __floats2half2_rn(psum[2], psum[3]);
        __half2 h2 = __floats2half2_rn(psum[4], psum[5]);
        __half2 h3 = __floats2half2_rn(psum[6], psum[7]);
        pa[0] = *(u32*)&h0; pa[1] = *(u32*)&h1;
        pa[2] = *(u32*)&h2; pa[3] = *(u32*)&h3;
    }

    float za[8][4];
    #pragma unroll
    for (int i = 0; i < 8; i++)
        #pragma unroll
        for (int t = 0; t < 4; t++) za[i][t] = 0.f;
    #pragma unroll
    for (int nb4 = 0; nb4 < 4; nb4++) {
        mma16816(za[nb4*2+0], pa, &vb[nb4][0]);
        mma16816(za[nb4*2+1], pa, &vb[nb4][2]);
    }

    {
        const int r0 = lane >> 2;
        const int c0 = (lane & 3) * 2;
        const size_t rowbase = ((size_t)b * SS) * EE;
        const int e0 = ((sp & 15) << 6);
        #pragma unroll
        for (int nb = 0; nb < 8; nb++) {
            int d = nb * 8 + c0;
            __half2 lo = __floats2half2_rn(za[nb][0], za[nb][1]);
            __half2 hi = __floats2half2_rn(za[nb][2], za[nb][3]);
            int s0f = r0 * 128 + (sp >> 4);
            int s1f = (r0 + 8) * 128 + (sp >> 4);
            *(__half2*)(z + rowbase + (size_t)s0f * EE + e0 + d) = lo;
            *(__half2*)(z + rowbase + (size_t)s1f * EE + e0 + d) = hi;
        }
    }
}

// ───────── host ─────────
typedef CUresult (*PFN_encode)(
    CUtensorMap*, CUtensorMapDataType, cuuint32_t, void*,
    const cuuint64_t*, const cuuint64_t*, const cuuint32_t*, const cuuint32_t*,
    CUtensorMapInterleave, CUtensorMapSwizzle, CUtensorMapL2promotion,
    CUtensorMapFloatOOBfill);

static CUtensorMap mk_map16(PFN_encode enc, void* base, u64 rows, u32 boxrows) {
    CUtensorMap m;
    cuuint64_t dims[2]    = {(cuuint64_t)EE, rows};
    cuuint64_t strides[1] = {(cuuint64_t)EE * 2};
    cuuint32_t box[2]     = {64u, boxrows};
    cuuint32_t es[2]      = {1u, 1u};
    enc(&m, CU_TENSOR_MAP_DATA_TYPE_FLOAT16, 2, base, dims, strides, box, es,
        CU_TENSOR_MAP_INTERLEAVE_NONE, CU_TENSOR_MAP_SWIZZLE_128B,
        CU_TENSOR_MAP_L2_PROMOTION_L2_128B, CU_TENSOR_MAP_FLOAT_OOB_FILL_NONE);
    return m;
}

extern "C" void kernel_launch(void* const* d_in, const int* in_sizes, int n_in,
                              void* d_out, int out_size)
{
    const float* x  = (const float*)d_in[0];
    const float* Wq = (const float*)d_in[1];
    const float* bq = (const float*)d_in[2];
    const float* Wk = (const float*)d_in[3];
    const float* bk = (const float*)d_in[4];
    const float* Wv = (const float*)d_in[5];
    const float* bv = (const float*)d_in[6];
    const float* Wo = (const float*)d_in[7];
    const float* bo = (const float*)d_in[8];
    float* out = (float*)d_out;

    float *pbqkv;
    __half *pqf, *pkvf, *pz, *xh, *wqkv, *wo;
    cudaGetSymbolAddress((void**)&pqf,  g_qf);
    cudaGetSymbolAddress((void**)&pkvf, g_kvf);
    cudaGetSymbolAddress((void**)&pz,   g_z);
    cudaGetSymbolAddress((void**)&pbqkv, g_bqkv);
    cudaGetSymbolAddress((void**)&xh, g_xh);
    cudaGetSymbolAddress((void**)&wqkv, g_wqkv);
    cudaGetSymbolAddress((void**)&wo, g_wo);

    PFN_encode enc = 0;
    cudaDriverEntryPointQueryResult qr;
    cudaGetDriverEntryPoint("cuTensorMapEncodeTiled", (void**)&enc,
                            cudaEnableDefault, &qr);

    CUtensorMap mXh  = mk_map16(enc, xh, MM, 128);
    CUtensorMap mZ64 = mk_map16(enc, pz, MM, 64);
    CUtensorMap mW   = mk_map16(enc, wqkv, NQKV, 256);
    CUtensorMap mO   = mk_map16(enc, wo, EE, 256);

    const u32 GS_QKV = 4 * (128*128 + 32768) + 64;   // MA=4 stage layout
    const u32 GS_O   = 4 * ( 64*128 + 32768) + 64;   // MA=2
    cudaFuncSetAttribute((const void*)hgemm1<1,4,1>,
                         cudaFuncAttributeMaxDynamicSharedMemorySize, GS_QKV);
    cudaFuncSetAttribute((const void*)hgemm1<0,2,0>,
                         cudaFuncAttributeMaxDynamicSharedMemorySize, GS_O);
    cudaFuncSetAttribute(attn_kernel, cudaFuncAttributeMaxDynamicSharedMemorySize, ASMEM);

    dim3 blk(256);
    conv_all<<<C_WO/256, blk>>>(x, Wq, Wk, Wv, Wo, xh, wqkv, wo);
    bias_concat<<<(NQKV + 255)/256, blk>>>(bq, bk, bv, pbqkv);

    // fused Q|K|V projection; q → fragment layout, k|v → kvf
    hgemm1<1,4,1><<<dim3(NQKV/256, MM/128), blk, GS_QKV>>>(
        mXh, mW, pbqkv, nullptr, pqf, pkvf, NQKV, EE, 0);

    // tensor-core attention, q frags direct from global
    attn_kernel<<<MM/ATOK, blk, ASMEM>>>(pqf, pkvf, pz);

    // O projection: BM=64 for wave quantization
    hgemm1<0,2,0><<<dim3(EE/256, MM/64), blk, GS_O>>>(
        mZ64, mO, bo, out, nullptr, nullptr, EE, EE, 0);
}

// round 17
// speedup vs baseline: 1.0171x; 1.0171x over previous
#include <cuda_runtime.h>
#include <cuda.h>
#include <cuda_fp16.h>

typedef unsigned int u32;
typedef unsigned long long u64;

#define BB 4
#define SS 2048
#define EE 1024
#define HH 16
#define DD 64
#define QQ 4
#define MM (BB*SS)     /* 8192 tokens */
#define NQKV 6144

// ───────── scratch (allocation-free rule: __device__ globals) ─────────
__device__ __half g_qkv[(size_t)MM * NQKV];    // fused q|k|v projection, fp16
__device__ __half g_z  [(size_t)MM * EE];      // attn output, per-token layout [tok][h*64+d]
__device__ float  g_bqkv[NQKV];

__device__ __half g_xh[(size_t)MM*EE];
__device__ __half g_wqkv[(size_t)NQKV*EE];
__device__ __half g_wo[(size_t)EE*EE];

__device__ __forceinline__ u32 smem_u32(const void* p) {
    u32 a;
    asm("{ .reg .u64 t; cvta.to.shared.u64 t, %1; cvt.u32.u64 %0, t; }"
        : "=r"(a) : "l"(p));
    return a;
}
__device__ __forceinline__ void ldsm4(u32 addr, u32* r) {
    asm volatile("ldmatrix.sync.aligned.m8n8.x4.shared.b16 {%0,%1,%2,%3}, [%4];"
                 : "=r"(r[0]), "=r"(r[1]), "=r"(r[2]), "=r"(r[3]) : "r"(addr));
}
__device__ __forceinline__ void ldsm4t(u32 addr, u32* r) {
    asm volatile("ldmatrix.sync.aligned.m8n8.x4.trans.shared.b16 {%0,%1,%2,%3}, [%4];"
                 : "=r"(r[0]), "=r"(r[1]), "=r"(r[2]), "=r"(r[3]) : "r"(addr));
}
__device__ __forceinline__ void mma16816(float* c, const u32* a, const u32* b) {
    asm volatile(
        "mma.sync.aligned.m16n8k16.row.col.f32.f16.f16.f32 "
        "{%0,%1,%2,%3}, {%4,%5,%6,%7}, {%8,%9}, {%0,%1,%2,%3};"
        : "+f"(c[0]), "+f"(c[1]), "+f"(c[2]), "+f"(c[3])
        : "r"(a[0]), "r"(a[1]), "r"(a[2]), "r"(a[3]), "r"(b[0]), "r"(b[1]));
}
__device__ __forceinline__ void tma2d(u32 saddr, const CUtensorMap* m,
                                      int cx, int cy, u32 mbar) {
    asm volatile(
        "cp.async.bulk.tensor.2d.shared::cta.global.tile.mbarrier::complete_tx::bytes "
        "[%0], [%1, {%2, %3}], [%4];"
        :: "r"(saddr), "l"(m), "r"(cx), "r"(cy), "r"(mbar) : "memory");
}
__device__ __forceinline__ void tma3d(u32 saddr, const CUtensorMap* m,
                                      int cx, int cy, int cz, u32 mbar) {
    asm volatile(
        "cp.async.bulk.tensor.3d.shared::cta.global.tile.mbarrier::complete_tx::bytes "
        "[%0], [%1, {%2, %3, %4}], [%5];"
        :: "r"(saddr), "l"(m), "r"(cx), "r"(cy), "r"(cz), "r"(mbar) : "memory");
}
#define MBAR_INIT(addr, cnt) \
    asm volatile("mbarrier.init.shared.b64 [%0], %1;" :: "r"(addr), "r"(cnt) : "memory")
#define MBAR_EXPECT(addr, bytes) \
    asm volatile("mbarrier.arrive.expect_tx.shared.b64 _, [%0], %1;" \
                 :: "r"(addr), "r"(bytes) : "memory")
__device__ __forceinline__ void mbar_wait(u32 addr, u32 parity) {
    asm volatile(
        "{\n\t.reg .pred P;\n\t"
        "W%=:\n\t"
        "mbarrier.try_wait.parity.acquire.cta.shared::cta.b64 P, [%0], %1, 0x989680;\n\t"
        "@P bra D%=;\n\t"
        "bra W%=;\n\t"
        "D%=:\n\t}"
        :: "r"(addr), "r"(parity) : "memory");
}
#define SWZ(off) ((u32)(off) ^ ((((u32)(off)) >> 3) & 0x70))

// ───────── fused fp32→fp16 conversion ─────────
#define C_X  2097152
#define C_WQ (C_X + 1048576)
#define C_WK (C_WQ + 262144)
#define C_WV (C_WK + 262144)
#define C_WO (C_WV + 262144)

__global__ __launch_bounds__(256) void conv_all(
    const float* __restrict__ x,  const float* __restrict__ Wq,
    const float* __restrict__ Wk, const float* __restrict__ Wv,
    const float* __restrict__ Wo,
    __half* __restrict__ xh, __half* __restrict__ wqkv, __half* __restrict__ wo)
{
    int i = blockIdx.x * blockDim.x + threadIdx.x;
    const float* s; __half* d; int off;
    if (i < C_X)       { s = x;  d = xh;                           off = i; }
    else if (i < C_WQ) { s = Wq; d = wqkv;                         off = i - C_X; }
    else if (i < C_WK) { s = Wk; d = wqkv + (size_t)4096*EE;       off = i - C_WQ; }
    else if (i < C_WV) { s = Wv; d = wqkv + (size_t)5120*EE;       off = i - C_WK; }
    else               { s = Wo; d = wo;                           off = i - C_WV; }
    float4 v = ((const float4*)s)[off];
    ushort4 ho;
    ho.x = __half_as_ushort(__float2half_rn(v.x));
    ho.y = __half_as_ushort(__float2half_rn(v.y));
    ho.z = __half_as_ushort(__float2half_rn(v.z));
    ho.w = __half_as_ushort(__float2half_rn(v.w));
    ((ushort4*)d)[off] = ho;
}

__global__ __launch_bounds__(256) void bias_concat(
    const float* __restrict__ bq, const float* __restrict__ bk,
    const float* __restrict__ bv, float* __restrict__ dst)
{
    int i = blockIdx.x * blockDim.x + threadIdx.x;
    if (i >= NQKV) return;
    float v;
    if (i < 4096)      v = bq[i];
    else if (i < 5120) v = bk[i - 4096];
    else               v = bv[i - 5120];
    dst[i] = v;
}

// ═════ 1-PASS fp16 GEMM, 4-stage TMA, BM=128.
//       A3D: A-side via 3D tensor map (z gather: cx=h*64, cy=chunk, cz=b*128). ═════
#define CHK 64
#define ABYT 16384u
#define STB1 49152u
#define S1_CTRL (4u*STB1)
#define GSMEM1 (4*49152 + 64)

template<int OUT16, int A3D>
__global__ __launch_bounds__(256, 1) void hgemm1(
    const __grid_constant__ CUtensorMap tA,
    const __grid_constant__ CUtensorMap tB,
    const float* __restrict__ bias, void* __restrict__ Cv,
    int N_, int K, int ny0)
{
    extern __shared__ __align__(1024) char smem[];
    const u32 sb   = smem_u32(smem);
    const int tid  = threadIdx.x;
    const int wid  = tid >> 5;
    const int lane = tid & 31;
    const int m0   = blockIdx.y * 128;
    const int n0   = blockIdx.x * 256;
    const int wm   = (wid & 1) * 64;
    const int wn   = (wid >> 1) * 64;
    const int nch  = K / CHK;

    float acc[4][8][4];
    #pragma unroll
    for (int i = 0; i < 4; i++)
        #pragma unroll
        for (int j = 0; j < 8; j++)
            #pragma unroll
            for (int t = 0; t < 4; t++) acc[i][j][t] = 0.f;

    if (tid == 0) {
        #pragma unroll
        for (int s = 0; s < 4; s++) MBAR_INIT(sb + S1_CTRL + s * 8, 1);
    }
    __syncthreads();

    auto issue = [&](int c) {
        if (tid == 0) {
            const int st   = c & 3;
            const u32 mbar = sb + S1_CTRL + st * 8;
            const u32 s0   = sb + st * STB1;
            MBAR_EXPECT(mbar, 49152u);
            if (A3D) {
                // blockIdx.y = b*16 + h; gather z rows (b,h,t16) for k-chunk c
                int cx = (blockIdx.y & 15) * 64;
                int cz = (blockIdx.y >> 4) * 128;
                tma3d(s0, &tA, cx, c, cz, mbar);
            } else {
                tma2d(s0, &tA, c * CHK, m0, mbar);
            }
            tma2d(s0 + ABYT, &tB, c * CHK, ny0 + n0, mbar);
        }
    };

    issue(0); issue(1); issue(2); issue(3);

    for (int c = 0; c < nch; c++) {
        const int st = c & 3;
        mbar_wait(sb + S1_CTRL + st * 8, (c >> 2) & 1);
        const u32 s0 = sb + st * STB1;

        #pragma unroll
        for (int ks = 0; ks < 4; ks++) {
            const int k0 = ks * 16;
            u32 a[4][4], b[4][4];
            #pragma unroll
            for (int ma = 0; ma < 4; ma++) {
                int row  = wm + ma * 16 + ((lane >> 3) & 1) * 8 + (lane & 7);
                int colB = (k0 + (lane >> 4) * 8) * 2;
                ldsm4(s0 + SWZ(row * 128 + colB), a[ma]);
            }
            #pragma unroll
            for (int j = 0; j < 4; j++) {
                int row  = wn + j * 16 + (lane >> 4) * 8 + (lane & 7);
                int colB = (k0 + ((lane >> 3) & 1) * 8) * 2;
                ldsm4(s0 + ABYT + SWZ(row * 128 + colB), b[j]);
            }
            #pragma unroll
            for (int j = 0; j < 4; j++)
                #pragma unroll
                for (int ma = 0; ma < 4; ma++) {
                    mma16816(acc[ma][j*2+0], a[ma], &b[j][0]);
                    mma16816(acc[ma][j*2+1], a[ma], &b[j][2]);
                }
        }
        __syncthreads();
        if (c + 4 < nch) issue(c + 4);
    }

    #pragma unroll
    for (int ma = 0; ma < 4; ma++) {
        #pragma unroll
        for (int nb = 0; nb < 8; nb++) {
            int row = m0 + wm + ma * 16 + (lane >> 2);
            int col = n0 + wn + nb * 8 + (lane & 3) * 2;
            float b0 = bias[col], b1 = bias[col + 1];
            float v00 = acc[ma][nb][0] + b0, v01 = acc[ma][nb][1] + b1;
            float v10 = acc[ma][nb][2] + b0, v11 = acc[ma][nb][3] + b1;
            if (OUT16) {
                __half* C = (__half*)Cv;
                *(__half2*)(C + (size_t)row * N_ + col)       = __floats2half2_rn(v00, v01);
                *(__half2*)(C + (size_t)(row + 8) * N_ + col) = __floats2half2_rn(v10, v11);
            } else {
                float* C = (float*)Cv;
                *(float2*)(C + (size_t)row * N_ + col)       = make_float2(v00, v01);
                *(float2*)(C + (size_t)(row + 8) * N_ + col) = make_float2(v10, v11);
            }
        }
    }
}

// ───────── attention v7: per-warp token, warp-private staging, contiguous z ─────
#define ATOK 8
#define TOKB 12288
#define ASMEM (ATOK*TOKB)

__global__ __launch_bounds__(256) void attn_kernel(
    const __half* __restrict__ qkv, __half* __restrict__ z)
{
    extern __shared__ __align__(1024) char smem[];
    const u32 sb   = smem_u32(smem);
    const int tid  = threadIdx.x;
    const int lane = tid & 31;
    const int w    = tid >> 5;
    const int n    = blockIdx.x * ATOK + w;
    const u32 tb   = sb + w * TOKB;

    // warp-private staging: 768 uint4 (full q|k|v row), 24 per lane
    {
        const uint4* src = (const uint4*)qkv + (size_t)n * 768;
        #pragma unroll
        for (int i = 0; i < 24; i++) {
            int idx = lane + i * 32;
            uint4 val = src[idx];
            *(uint4*)(smem + (u32)w * TOKB + SWZ(idx * 16)) = val;
        }
    }
    __syncwarp();

    // k b-frags (rows 64..79)
    u32 kb[4][4];
    #pragma unroll
    for (int ks = 0; ks < 4; ks++) {
        int row  = 64 + (lane >> 4) * 8 + (lane & 7);
        int colB = (ks * 16 + ((lane >> 3) & 1) * 8) * 2;
        ldsm4(tb + SWZ(row * 128 + colB), kb[ks]);
    }
    // v b-frags via trans ldsm (rows 80..95)
    u32 vb[4][4];
    #pragma unroll
    for (int nb4 = 0; nb4 < 4; nb4++) {
        int row  = 80 + (lane & 15);
        int colB = (nb4 * 16 + (lane >> 4) * 8) * 2;
        ldsm4t(tb + SWZ(row * 128 + colB), vb[nb4]);
    }

    float psum[8];
    #pragma unroll
    for (int i = 0; i < 8; i++) psum[i] = 0.f;

    #pragma unroll
    for (int qi = 0; qi < QQ; qi++) {
        u32 qa[4][4];
        #pragma unroll
        for (int ks = 0; ks < 4; ks++) {
            int row  = qi * 16 + ((lane >> 3) & 1) * 8 + (lane & 7);
            int colB = (ks * 16 + (lane >> 4) * 8) * 2;
            ldsm4(tb + SWZ(row * 128 + colB), qa[ks]);
        }
        float sc[2][4];
        #pragma unroll
        for (int t = 0; t < 4; t++) { sc[0][t] = 0.f; sc[1][t] = 0.f; }
        #pragma unroll
        for (int ks = 0; ks < 4; ks++) {
            mma16816(sc[0], qa[ks], &kb[ks][0]);
            mma16816(sc[1], qa[ks], &kb[ks][2]);
        }
        #pragma unroll
        for (int t = 0; t < 4; t++) { sc[0][t] *= 0.125f; sc[1][t] *= 0.125f; }
        float m0 = fmaxf(fmaxf(sc[0][0], sc[0][1]), fmaxf(sc[1][0], sc[1][1]));
        float m1 = fmaxf(fmaxf(sc[0][2], sc[0][3]), fmaxf(sc[1][2], sc[1][3]));
        #pragma unroll
        for (int o = 1; o <= 2; o <<= 1) {
            m0 = fmaxf(m0, __shfl_xor_sync(~0u, m0, o));
            m1 = fmaxf(m1, __shfl_xor_sync(~0u, m1, o));
        }
        float e00 = __expf(sc[0][0] - m0), e01 = __expf(sc[0][1] - m0);
        float e10 = __expf(sc[1][0] - m0), e11 = __expf(sc[1][1] - m0);
        float f00 = __expf(sc[0][2] - m1), f01 = __expf(sc[0][3] - m1);
        float f10 = __expf(sc[1][2] - m1), f11 = __expf(sc[1][3] - m1);
        float s0 = e00 + e01 + e10 + e11;
        float s1 = f00 + f01 + f10 + f11;
        #pragma unroll
        for (int o = 1; o <= 2; o <<= 1) {
            s0 += __shfl_xor_sync(~0u, s0, o);
            s1 += __shfl_xor_sync(~0u, s1, o);
        }
        float i0 = 1.f / s0, i1 = 1.f / s1;
        psum[0] += e00 * i0; psum[1] += e01 * i0;
        psum[2] += f00 * i1; psum[3] += f01 * i1;
        psum[4] += e10 * i0; psum[5] += e11 * i0;
        psum[6] += f10 * i1; psum[7] += f11 * i1;
    }

    u32 pa[4];
    {
        __half2 h0 = __floats2half2_rn(psum[0], psum[1]);
        __half2 h1 = __floats2half2_rn(psum[2], psum[3]);
        __half2 h2 = __floats2half2_rn(psum[4], psum[5]);
        __half2 h3 = __floats2half2_rn(psum[6], psum[7]);
        pa[0] = *(u32*)&h0; pa[1] = *(u32*)&h1;
        pa[2] = *(u32*)&h2; pa[3] = *(u32*)&h3;
    }

    float za[8][4];
    #pragma unroll
    for (int i = 0; i < 8; i++)
        #pragma unroll
        for (int t = 0; t < 4; t++) za[i][t] = 0.f;
    #pragma unroll
    for (int nb4 = 0; nb4 < 4; nb4++) {
        mma16816(za[nb4*2+0], pa, &vb[nb4][0]);
        mma16816(za[nb4*2+1], pa, &vb[nb4][2]);
    }

    // contiguous per-token z write: z[n][h*64 + d]  (shuffle moved into O-GEMM TMA)
    {
        const int h0 = lane >> 2;             // rows h0, h0+8
        const int c0 = (lane & 3) * 2;
        __half* zp = z + (size_t)n * EE;
        #pragma unroll
        for (int nb = 0; nb < 8; nb++) {
            int d = nb * 8 + c0;
            *(__half2*)(zp + h0 * 64 + d)       = __floats2half2_rn(za[nb][0], za[nb][1]);
            *(__half2*)(zp + (h0 + 8) * 64 + d) = __floats2half2_rn(za[nb][2], za[nb][3]);
        }
    }
}

// ───────── host ─────────
typedef CUresult (*PFN_encode)(
    CUtensorMap*, CUtensorMapDataType, cuuint32_t, void*,
    const cuuint64_t*, const cuuint64_t*, const cuuint32_t*, const cuuint32_t*,
    CUtensorMapInterleave, CUtensorMapSwizzle, CUtensorMapL2promotion,
    CUtensorMapFloatOOBfill);

static CUtensorMap mk_map16(PFN_encode enc, void* base, u64 rows, u32 boxrows) {
    CUtensorMap m;
    cuuint64_t dims[2]    = {(cuuint64_t)EE, rows};
    cuuint64_t strides[1] = {(cuuint64_t)EE * 2};
    cuuint32_t box[2]     = {64u, boxrows};
    cuuint32_t es[2]      = {1u, 1u};
    enc(&m, CU_TENSOR_MAP_DATA_TYPE_FLOAT16, 2, base, dims, strides, box, es,
        CU_TENSOR_MAP_INTERLEAVE_NONE, CU_TENSOR_MAP_SWIZZLE_128B,
        CU_TENSOR_MAP_L2_PROMOTION_L2_128B, CU_TENSOR_MAP_FLOAT_OOB_FILL_NONE);
    return m;
}

// 3D gather map for shuffled z: dims {1024 (h*64+d), 16 (s16), 512 (b*128+t16)}
static CUtensorMap mk_map_z3(PFN_encode enc, void* base) {
    CUtensorMap m;
    cuuint64_t dims[3]    = {1024, 16, 512};
    cuuint64_t strides[2] = {1024 * 2, 16 * 1024 * 2};   // s16: +1 token; t16: +16 tokens
    cuuint32_t box[3]     = {64u, 1u, 128u};
    cuuint32_t es[3]      = {1u, 1u, 1u};
    enc(&m, CU_TENSOR_MAP_DATA_TYPE_FLOAT16, 3, base, dims, strides, box, es,
        CU_TENSOR_MAP_INTERLEAVE_NONE, CU_TENSOR_MAP_SWIZZLE_128B,
        CU_TENSOR_MAP_L2_PROMOTION_L2_128B, CU_TENSOR_MAP_FLOAT_OOB_FILL_NONE);
    return m;
}

extern "C" void kernel_launch(void* const* d_in, const int* in_sizes, int n_in,
                              void* d_out, int out_size)
{
    const float* x  = (const float*)d_in[0];
    const float* Wq = (const float*)d_in[1];
    const float* bq = (const float*)d_in[2];
    const float* Wk = (const float*)d_in[3];
    const float* bk = (const float*)d_in[4];
    const float* Wv = (const float*)d_in[5];
    const float* bv = (const float*)d_in[6];
    const float* Wo = (const float*)d_in[7];
    const float* bo = (const float*)d_in[8];
    float* out = (float*)d_out;

    float *pbqkv;
    __half *pqkv, *pz, *xh, *wqkv, *wo;
    cudaGetSymbolAddress((void**)&pqkv, g_qkv);
    cudaGetSymbolAddress((void**)&pz,   g_z);
    cudaGetSymbolAddress((void**)&pbqkv, g_bqkv);
    cudaGetSymbolAddress((void**)&xh, g_xh);
    cudaGetSymbolAddress((void**)&wqkv, g_wqkv);
    cudaGetSymbolAddress((void**)&wo, g_wo);

    PFN_encode enc = 0;
    cudaDriverEntryPointQueryResult qr;
    cudaGetDriverEntryPoint("cuTensorMapEncodeTiled", (void**)&enc,
                            cudaEnableDefault, &qr);

    CUtensorMap mXh = mk_map16(enc, xh, MM, 128);
    CUtensorMap mW  = mk_map16(enc, wqkv, NQKV, 256);
    CUtensorMap mO  = mk_map16(enc, wo, EE, 256);
    CUtensorMap mZ3 = mk_map_z3(enc, pz);

    cudaFuncSetAttribute((const void*)hgemm1<1,0>,
                         cudaFuncAttributeMaxDynamicSharedMemorySize, GSMEM1);
    cudaFuncSetAttribute((const void*)hgemm1<0,1>,
                         cudaFuncAttributeMaxDynamicSharedMemorySize, GSMEM1);
    cudaFuncSetAttribute(attn_kernel, cudaFuncAttributeMaxDynamicSharedMemorySize, ASMEM);

    dim3 blk(256);
    conv_all<<<C_WO/256, blk>>>(x, Wq, Wk, Wv, Wo, xh, wqkv, wo);
    bias_concat<<<(NQKV + 255)/256, blk>>>(bq, bk, bv, pbqkv);

    // fused Q|K|V projection: one GEMM, N=6144, contiguous fp16 out
    hgemm1<1,0><<<dim3(NQKV/256, MM/128), blk, GSMEM1>>>(
        mXh, mW, pbqkv, pqkv, NQKV, EE, 0);

    // tensor-core attention; z written contiguous per token
    attn_kernel<<<MM/ATOK, blk, ASMEM>>>(pqkv, pz);

    // O projection: A-side = 3D TMA gather implementing the head shuffle
    hgemm1<0,1><<<dim3(EE/256, MM/128), blk, GSMEM1>>>(
        mZ3, mO, bo, out, EE, EE, 0);
}